// round 14
// baseline (speedup 1.0000x reference)
#include <cuda_runtime.h>
#include <cuda_fp16.h>
#include <cstdint>
#include <math.h>

#define BB   32
#define NSEQ 1023
#define LL   512
#define HH   1024
#define SHD  50
#define SYNR 128
#define INTN 511

// ---- big kernel: 512 threads, 16 warps, warp tile 32x64, BK=64, 4 stages ----
#define MT     128
#define NTILE  256
#define BK     64
#define STAGES 4
#define A_STR 72
#define B_STR 264
#define AS_BYTES (MT * A_STR * 2)
#define BS_BYTES (BK * B_STR * 2)
#define STAGE_BYTES (AS_BYTES + BS_BYTES)
#define DSMEM (STAGES * STAGE_BYTES)

// ---- small kernel: 32x128 tile, BK=64, 4 stages ----
#define MT_S    32
#define NTILE_S 128
#define STAGES_S 4
#define BS_STR_S 136
#define AS_BYTES_S (MT_S * A_STR * 2)
#define BS_BYTES_S (BK * BS_STR_S * 2)
#define STAGE_BYTES_S (AS_BYTES_S + BS_BYTES_S)
#define DSMEM_S (STAGES_S * STAGE_BYTES_S)

#define KP_COMP 2112
#define KP_DEC  2176
#define KP_LG   1088
#define KP_PRE  1152     /* syn_l(64) + syn_r(64) + up(1024) */

// ---------------- scratch ----------------
__device__ __half g_up   [(size_t)BB * NSEQ * HH];
__device__ __half g_down [(size_t)BB * NSEQ * HH];
__device__ __half g_wcomp[(size_t)KP_COMP * 1024];
// g_wdec row blocks: [0,64)=syn_l W, [64,128)=syn_r W, [128,1152)=UP W, [1152,2176)=DOWN W
__device__ __half g_wdec [(size_t)KP_DEC  * 2048];
__device__ __half g_wleaf[(size_t)KP_LG   * 1024];
__device__ __half g_wgrev[(size_t)KP_LG   * 1024];
__device__ __half g_syn  [(size_t)SYNR * 64];
__device__ __half g_leafA[(size_t)BB * LL * KP_LG];
__device__ float  g_partial[(size_t)8 * 2048 * 2048];
__device__ float  g_pre[(size_t)BB * INTN * 2048];

// ---------------- helpers ----------------
__device__ __forceinline__ uint32_t smem_u32(const void* p) {
    uint32_t a;
    asm("{ .reg .u64 t; cvta.to.shared.u64 t, %1; cvt.u32.u64 %0, t; }" : "=r"(a) : "l"(p));
    return a;
}
#define CP_ASYNC16(dst, src) \
    asm volatile("cp.async.cg.shared.global [%0], [%1], 16;" :: "r"(dst), "l"(src))
#define CP_COMMIT() asm volatile("cp.async.commit_group;" ::: "memory")
#define CP_WAIT2()  asm volatile("cp.async.wait_group 2;" ::: "memory")

#define LDSM_X4(R, addr) \
    asm volatile("ldmatrix.sync.aligned.m8n8.x4.shared.b16 {%0,%1,%2,%3}, [%4];" \
        : "=r"((R)[0]), "=r"((R)[1]), "=r"((R)[2]), "=r"((R)[3]) : "r"(addr))
#define LDSM_X4T(R, addr) \
    asm volatile("ldmatrix.sync.aligned.m8n8.x4.trans.shared.b16 {%0,%1,%2,%3}, [%4];" \
        : "=r"((R)[0]), "=r"((R)[1]), "=r"((R)[2]), "=r"((R)[3]) : "r"(addr))

#define MMA16816(c, a, b0, b1) \
    asm volatile("mma.sync.aligned.m16n8k16.row.col.f32.f16.f16.f32 " \
        "{%0,%1,%2,%3}, {%4,%5,%6,%7}, {%8,%9}, {%0,%1,%2,%3};" \
        : "+f"((c)[0]), "+f"((c)[1]), "+f"((c)[2]), "+f"((c)[3]) \
        : "r"((a)[0]), "r"((a)[1]), "r"((a)[2]), "r"((a)[3]), "r"(b0), "r"(b1))

enum { M_LEAF = 0, M_UP, M_GREV, M_DOWN2, M_PRE };

struct GP {
    const __half* W;
    const float* bias;
    int ldw, M, Ktot, nph, node_base, node_cnt;
    int ph_start[4];      // BK-chunk units
    const int *x, *cue;   // cue slot carries pos for M_DOWN2/M_PRE
    const float* leafW;
    int Nout, kcpz;
    float* partial;
};

template<int MODE>
__device__ __forceinline__ void resolve_row(const GP& p, int r,
        const __half*& a0, const __half*& a1, const __half*& a2, const __half*& a3,
        const float*& ad, __half*& o) {
    a0 = p.W; a1 = p.W; a2 = p.W; a3 = p.W; ad = nullptr; o = nullptr;
    if (r >= p.M) return;
    if (MODE == M_LEAF) {
        int b = r >> 9, l = r & (LL - 1);
        int w = (LL - 1) + l;
        int c = p.cue[b * NSEQ + w];
        a0 = g_leafA + (size_t)r * KP_LG;
        ad = p.leafW + (size_t)(HH + c) * HH;
        o  = g_up + ((size_t)b * NSEQ + w) * HH;
    } else if (MODE == M_UP) {
        int b = r / p.node_cnt, n = p.node_base + r % p.node_cnt;
        a0 = g_syn + (size_t)p.x[b * NSEQ + n] * 64;
        a1 = g_up + ((size_t)b * NSEQ + 2 * n + 1) * HH;
        o  = g_up + ((size_t)b * NSEQ + n) * HH;
    } else if (MODE == M_GREV) {
        int b = r;
        a0 = g_up + (size_t)b * NSEQ * HH;
        a1 = g_syn + (size_t)p.x[b * NSEQ] * 64;
        o  = g_down + (size_t)b * NSEQ * HH;
    } else if (MODE == M_PRE) {
        int b = r / INTN, n = r % INTN;
        int cl = 2 * n + 1, cr = 2 * n + 2;
        const int* pp = p.cue;   // pos
        int si_l = (cl >= LL - 1) ? pp[b * LL + cl - (LL - 1)] : p.x[b * NSEQ + cl];
        int si_r = (cr >= LL - 1) ? pp[b * LL + cr - (LL - 1)] : p.x[b * NSEQ + cr];
        a0 = g_syn + (size_t)si_l * 64;
        a1 = g_syn + (size_t)si_r * 64;
        a2 = g_up + ((size_t)b * NSEQ + n) * HH;
        o  = reinterpret_cast<__half*>(g_pre + ((size_t)b * INTN + n) * 2048);
    } else { // M_DOWN2: A = down_n only; additive = g_pre row (has syn+up+bias)
        int b = r / p.node_cnt, n = p.node_base + r % p.node_cnt;
        a0 = g_down + ((size_t)b * NSEQ + n) * HH;
        ad = g_pre + ((size_t)b * INTN + n) * 2048;
        o  = g_down + ((size_t)b * NSEQ + 2 * n + 1) * HH;
    }
}

// ---------------- fused prep kernel ----------------
__device__ __forceinline__ void conv4(__half* dst, const float* src) {
    if (src) {
        float4 v = *reinterpret_cast<const float4*>(src);
        __half2* d = reinterpret_cast<__half2*>(dst);
        d[0] = __floats2half2_rn(v.x, v.y);
        d[1] = __floats2half2_rn(v.z, v.w);
    } else {
        *reinterpret_cast<uint2*>(dst) = make_uint2(0, 0);
    }
}

__global__ void prep_all(const float* __restrict__ compW, const float* __restrict__ decW,
                         const float* __restrict__ leafW, const float* __restrict__ grevW,
                         const float* __restrict__ syn) {
    const size_t S0 = (size_t)KP_COMP * 256;
    const size_t S1 = (size_t)KP_DEC  * 512;
    const size_t S2 = (size_t)KP_LG   * 256;
    const size_t S3 = (size_t)KP_LG   * 256;
    const size_t S4 = (size_t)SYNR * 64;
    const size_t total = S0 + S1 + S2 + S3 + S4;
    for (size_t i = (size_t)blockIdx.x * blockDim.x + threadIdx.x; i < total;
         i += (size_t)gridDim.x * blockDim.x) {
        if (i < S0) {
            int r = (int)(i >> 8), v = (int)(i & 255);
            const float* s;
            if (r < 50) s = compW + (size_t)r * 1024 + v * 4;
            else if (r < 64) s = nullptr;
            else s = compW + (size_t)(50 + r - 64) * 1024 + v * 4;
            conv4(g_wcomp + (size_t)r * 1024 + v * 4, s);
        } else if (i < S0 + S1) {
            size_t j = i - S0;
            int r = (int)(j >> 9), v = (int)(j & 511);
            const float* s;
            if (r < 50) s = decW + (size_t)r * 2048 + v * 4;                       // syn_l
            else if (r < 64) s = nullptr;
            else if (r < 114) s = decW + (size_t)(50 + r - 64) * 2048 + v * 4;     // syn_r
            else if (r < 128) s = nullptr;
            else if (r < 1152) s = decW + (size_t)(1124 + r - 128) * 2048 + v * 4; // UP part
            else s = decW + (size_t)(100 + r - 1152) * 2048 + v * 4;               // DOWN part
            conv4(g_wdec + (size_t)r * 2048 + v * 4, s);
        } else if (i < S0 + S1 + S2) {
            size_t j = i - S0 - S1;
            int r = (int)(j >> 8), v = (int)(j & 255);
            const float* s;
            if (r < 1024) s = leafW + (size_t)r * 1024 + v * 4;
            else if (r < 1074) s = leafW + (size_t)(1027 + r - 1024) * 1024 + v * 4;
            else s = nullptr;
            conv4(g_wleaf + (size_t)r * 1024 + v * 4, s);
        } else if (i < S0 + S1 + S2 + S3) {
            size_t j = i - S0 - S1 - S2;
            int r = (int)(j >> 8), v = (int)(j & 255);
            const float* s = (r < 1074) ? grevW + (size_t)r * 1024 + v * 4 : nullptr;
            conv4(g_wgrev + (size_t)r * 1024 + v * 4, s);
        } else {
            size_t j = i - S0 - S1 - S2 - S3;
            int r = (int)(j >> 6), c = (int)(j & 63);
            g_syn[(size_t)r * 64 + c] = (c < SHD) ? __float2half_rn(syn[(size_t)r * SHD + c])
                                                  : __ushort_as_half(0);
        }
    }
}

__global__ __launch_bounds__(256) void build_leafA(const int* __restrict__ x,
                                                   const int* __restrict__ pos,
                                                   const float* __restrict__ wemb,
                                                   const float* __restrict__ syn) {
    int row = blockIdx.x * 8 + (threadIdx.x >> 5);
    if (row >= BB * LL) return;
    int lane = threadIdx.x & 31;
    int b = row >> 9, l = row & (LL - 1);
    int w = (LL - 1) + l;
    int s = x[b * NSEQ + w];
    int pr = pos[b * LL + l];
    const float4* src = reinterpret_cast<const float4*>(wemb + (size_t)s * HH);
    __half* dst = g_leafA + (size_t)row * KP_LG;
    #pragma unroll
    for (int i = 0; i < 8; i++) {
        float4 v = src[lane + i * 32];
        reinterpret_cast<__half2*>(dst)[(lane + i * 32) * 2]     = __floats2half2_rn(v.x, v.y);
        reinterpret_cast<__half2*>(dst)[(lane + i * 32) * 2 + 1] = __floats2half2_rn(v.z, v.w);
    }
    {
        int c0 = lane * 2;
        float f0 = (c0     < SHD) ? syn[(size_t)pr * SHD + c0]     : 0.f;
        float f1 = (c0 + 1 < SHD) ? syn[(size_t)pr * SHD + c0 + 1] : 0.f;
        reinterpret_cast<__half2*>(dst + 1024)[lane] = __floats2half2_rn(f0, f1);
    }
}

// ---------------- big fp16 GEMM ----------------
template<int MODE, bool DOTANH>
__global__ __launch_bounds__(512) void hgemm(GP p) {
    __shared__ const __half* sAp[4][MT];
    __shared__ __half* sO[MT];
    __shared__ const float* sAdd[MT];
    extern __shared__ __align__(16) char dynraw[];

    const int tid = threadIdx.x;
    const int wid = tid >> 5;
    const int lane = tid & 31;
    const int rbase = blockIdx.y * MT;
    const int nblk = blockIdx.x * NTILE;

    if (tid < MT) {
        const __half *a0, *a1, *a2, *a3; const float* ad; __half* o;
        resolve_row<MODE>(p, rbase + tid, a0, a1, a2, a3, ad, o);
        sAp[0][tid] = a0; sAp[1][tid] = a1; sAp[2][tid] = a2; sAp[3][tid] = a3;
        sO[tid] = o; sAdd[tid] = ad;
    }
    __syncthreads();

    const int nc = p.Ktot / BK;
    const uint32_t dynB = smem_u32(dynraw);

    auto prefetch = [&](int c, int stage) {
        const uint32_t asB = dynB + stage * STAGE_BYTES;
        const uint32_t bsB = asB + AS_BYTES;
        int phidx = 0;
        #pragma unroll
        for (int q = 1; q < 4; q++) if (q < p.nph && c >= p.ph_start[q]) phidx = q;
        const int kloc = (c - p.ph_start[phidx]) * BK;
        #pragma unroll
        for (int i = 0; i < 2; i++) {
            int lin = i * 512 + tid;
            int row = lin >> 3, seg = lin & 7;
            CP_ASYNC16(asB + (row * A_STR + seg * 8) * 2, sAp[phidx][row] + kloc + seg * 8);
        }
        const __half* wsrc = p.W + (size_t)(c * BK) * p.ldw + nblk;
        #pragma unroll
        for (int i = 0; i < 4; i++) {
            int lin = i * 512 + tid;
            int row = lin >> 5, seg = lin & 31;
            CP_ASYNC16(bsB + (row * B_STR + seg * 8) * 2, wsrc + (size_t)row * p.ldw + seg * 8);
        }
    };

    const int warp_m = wid & 3;
    const int warp_n = wid >> 2;
    const uint32_t aLane = ((warp_m * 32 + (lane & 15)) * A_STR + (lane >> 4) * 8) * 2;
    const uint32_t bLane = ((lane & 15) * B_STR + warp_n * 64 + (lane >> 4) * 8) * 2;

    float cacc[2][8][4];
    #pragma unroll
    for (int i = 0; i < 2; i++)
        #pragma unroll
        for (int j = 0; j < 8; j++)
            #pragma unroll
            for (int e = 0; e < 4; e++) cacc[i][j][e] = 0.f;

    #pragma unroll
    for (int s = 0; s < STAGES - 1; s++) {
        if (s < nc) prefetch(s, s);
        CP_COMMIT();
    }

    for (int c = 0; c < nc; c++) {
        CP_WAIT2();
        __syncthreads();
        const int stage = c & (STAGES - 1);
        const uint32_t asB = dynB + stage * STAGE_BYTES;
        const uint32_t bsB = asB + AS_BYTES;
        #pragma unroll
        for (int kk = 0; kk < 4; kk++) {
            uint32_t af[2][4], bf[4][4];
            #pragma unroll
            for (int mf = 0; mf < 2; mf++)
                LDSM_X4(af[mf], asB + aLane + (mf * 16 * A_STR + kk * 16) * 2);
            #pragma unroll
            for (int nfp = 0; nfp < 4; nfp++)
                LDSM_X4T(bf[nfp], bsB + bLane + (kk * 16 * B_STR + nfp * 16) * 2);
            #pragma unroll
            for (int mf = 0; mf < 2; mf++)
                #pragma unroll
                for (int nfp = 0; nfp < 4; nfp++) {
                    MMA16816(cacc[mf][nfp * 2],     af[mf], bf[nfp][0], bf[nfp][1]);
                    MMA16816(cacc[mf][nfp * 2 + 1], af[mf], bf[nfp][2], bf[nfp][3]);
                }
        }
        int pc = c + STAGES - 1;
        if (pc < nc) prefetch(pc, pc & (STAGES - 1));
        CP_COMMIT();
    }

    {
        const int g = lane >> 2, t = lane & 3;
        #pragma unroll
        for (int mf = 0; mf < 2; mf++) {
            const int tr1 = warp_m * 32 + mf * 16 + g;
            const int tr2 = tr1 + 8;
            __half* o1 = sO[tr1];
            __half* o2 = sO[tr2];
            const float* ad1 = sAdd[tr1];
            const float* ad2 = sAdd[tr2];
            #pragma unroll
            for (int nf = 0; nf < 8; nf++) {
                const int col0 = nblk + warp_n * 64 + nf * 8 + t * 2;
                const float b0 = (MODE == M_DOWN2) ? 0.f : p.bias[col0];
                const float b1 = (MODE == M_DOWN2) ? 0.f : p.bias[col0 + 1];
                const float* cc = cacc[mf][nf];
                if (o1) {
                    float v0 = cc[0] + b0, v1 = cc[1] + b1;
                    if (ad1) { v0 += ad1[col0]; v1 += ad1[col0 + 1]; }
                    if (MODE == M_PRE) {
                        *reinterpret_cast<float2*>(reinterpret_cast<float*>(o1) + col0) =
                            make_float2(v0, v1);
                    } else {
                        if (DOTANH) { v0 = tanhf(v0); v1 = tanhf(v1); }
                        *reinterpret_cast<__half2*>(o1 + col0) = __floats2half2_rn(v0, v1);
                    }
                }
                if (o2) {
                    float v0 = cc[2] + b0, v1 = cc[3] + b1;
                    if (ad2) { v0 += ad2[col0]; v1 += ad2[col0 + 1]; }
                    if (MODE == M_PRE) {
                        *reinterpret_cast<float2*>(reinterpret_cast<float*>(o2) + col0) =
                            make_float2(v0, v1);
                    } else {
                        if (DOTANH) { v0 = tanhf(v0); v1 = tanhf(v1); }
                        *reinterpret_cast<__half2*>(o2 + col0) = __floats2half2_rn(v0, v1);
                    }
                }
            }
        }
    }
}

// ---------------- small-M fp16 GEMM with optional split-K ----------------
template<int MODE, bool DOTANH>
__global__ __launch_bounds__(256, 2) void hgemm_s(GP p) {
    __shared__ const __half* sAp[4][MT_S];
    __shared__ __half* sO[MT_S];
    __shared__ const float* sAdd[MT_S];
    extern __shared__ __align__(16) char dynraw[];

    const int tid = threadIdx.x;
    const int wid = tid >> 5;
    const int lane = tid & 31;
    const int rbase = blockIdx.y * MT_S;
    const int nblk = blockIdx.x * NTILE_S;

    if (tid < MT_S) {
        const __half *a0, *a1, *a2, *a3; const float* ad; __half* o;
        resolve_row<MODE>(p, rbase + tid, a0, a1, a2, a3, ad, o);
        sAp[0][tid] = a0; sAp[1][tid] = a1; sAp[2][tid] = a2; sAp[3][tid] = a3;
        sO[tid] = o; sAdd[tid] = ad;
    }
    __syncthreads();

    const int nc = p.Ktot / BK;
    int c0 = 0, ncc = nc;
    if (p.partial) {
        c0 = blockIdx.z * p.kcpz;
        ncc = nc - c0;
        if (ncc > p.kcpz) ncc = p.kcpz;
        if (ncc < 0) ncc = 0;
    }
    const uint32_t dynB = smem_u32(dynraw);

    auto prefetch = [&](int c, int stage) {
        const uint32_t asB = dynB + stage * STAGE_BYTES_S;
        const uint32_t bsB = asB + AS_BYTES_S;
        int phidx = 0;
        #pragma unroll
        for (int q = 1; q < 4; q++) if (q < p.nph && c >= p.ph_start[q]) phidx = q;
        const int kloc = (c - p.ph_start[phidx]) * BK;
        {
            int row = tid >> 3, seg = tid & 7;
            CP_ASYNC16(asB + (row * A_STR + seg * 8) * 2, sAp[phidx][row] + kloc + seg * 8);
        }
        const __half* wsrc = p.W + (size_t)(c * BK) * p.ldw + nblk;
        #pragma unroll
        for (int i = 0; i < 4; i++) {
            int lin = i * 256 + tid;
            int row = lin >> 4, seg = lin & 15;
            CP_ASYNC16(bsB + (row * BS_STR_S + seg * 8) * 2, wsrc + (size_t)row * p.ldw + seg * 8);
        }
    };

    const uint32_t aLane = ((lane & 15) * A_STR + (lane >> 4) * 8) * 2;
    const uint32_t bLane = ((lane & 15) * BS_STR_S + wid * 16 + (lane >> 4) * 8) * 2;

    float cacc[2][2][4];
    #pragma unroll
    for (int i = 0; i < 2; i++)
        #pragma unroll
        for (int j = 0; j < 2; j++)
            #pragma unroll
            for (int e = 0; e < 4; e++) cacc[i][j][e] = 0.f;

    #pragma unroll
    for (int s = 0; s < STAGES_S - 1; s++) {
        if (s < ncc) prefetch(c0 + s, s);
        CP_COMMIT();
    }

    for (int cc = 0; cc < ncc; cc++) {
        CP_WAIT2();
        __syncthreads();
        const int stage = cc & (STAGES_S - 1);
        const uint32_t asB = dynB + stage * STAGE_BYTES_S;
        const uint32_t bsB = asB + AS_BYTES_S;
        #pragma unroll
        for (int kk = 0; kk < 4; kk++) {
            uint32_t af[2][4], bf[4];
            #pragma unroll
            for (int mf = 0; mf < 2; mf++)
                LDSM_X4(af[mf], asB + aLane + (mf * 16 * A_STR + kk * 16) * 2);
            LDSM_X4T(bf, bsB + bLane + (kk * 16 * BS_STR_S) * 2);
            #pragma unroll
            for (int mf = 0; mf < 2; mf++) {
                MMA16816(cacc[mf][0], af[mf], bf[0], bf[1]);
                MMA16816(cacc[mf][1], af[mf], bf[2], bf[3]);
            }
        }
        int pcc = cc + STAGES_S - 1;
        if (pcc < ncc) prefetch(c0 + pcc, pcc & (STAGES_S - 1));
        CP_COMMIT();
    }

    {
        const int g = lane >> 2, t = lane & 3;
        if (p.partial) {
            float* base = p.partial + (size_t)blockIdx.z * p.M * p.Nout;
            #pragma unroll
            for (int mf = 0; mf < 2; mf++) {
                const int r1 = rbase + mf * 16 + g;
                const int r2 = r1 + 8;
                #pragma unroll
                for (int nf = 0; nf < 2; nf++) {
                    const int col0 = nblk + wid * 16 + nf * 8 + t * 2;
                    const float* cc = cacc[mf][nf];
                    if (r1 < p.M)
                        *reinterpret_cast<float2*>(base + (size_t)r1 * p.Nout + col0) =
                            make_float2(cc[0], cc[1]);
                    if (r2 < p.M)
                        *reinterpret_cast<float2*>(base + (size_t)r2 * p.Nout + col0) =
                            make_float2(cc[2], cc[3]);
                }
            }
        } else {
            #pragma unroll
            for (int mf = 0; mf < 2; mf++) {
                const int tr1 = mf * 16 + g;
                const int tr2 = tr1 + 8;
                __half* o1 = sO[tr1];
                __half* o2 = sO[tr2];
                const float* ad1 = sAdd[tr1];
                const float* ad2 = sAdd[tr2];
                #pragma unroll
                for (int nf = 0; nf < 2; nf++) {
                    const int col0 = nblk + wid * 16 + nf * 8 + t * 2;
                    const float b0 = (MODE == M_DOWN2) ? 0.f : p.bias[col0];
                    const float b1 = (MODE == M_DOWN2) ? 0.f : p.bias[col0 + 1];
                    const float* cc = cacc[mf][nf];
                    if (o1) {
                        float v0 = cc[0] + b0, v1 = cc[1] + b1;
                        if (ad1) { v0 += ad1[col0]; v1 += ad1[col0 + 1]; }
                        if (DOTANH) { v0 = tanhf(v0); v1 = tanhf(v1); }
                        *reinterpret_cast<__half2*>(o1 + col0) = __floats2half2_rn(v0, v1);
                    }
                    if (o2) {
                        float v0 = cc[2] + b0, v1 = cc[3] + b1;
                        if (ad2) { v0 += ad2[col0]; v1 += ad2[col0 + 1]; }
                        if (DOTANH) { v0 = tanhf(v0); v1 = tanhf(v1); }
                        *reinterpret_cast<__half2*>(o2 + col0) = __floats2half2_rn(v0, v1);
                    }
                }
            }
        }
    }
}

// ---------------- split-K reduction: bias/additive + slices + tanh ----------------
template<int MODE>
__global__ __launch_bounds__(256) void reduceK(GP p, int nz) {
    int idx = blockIdx.x * 256 + threadIdx.x;
    int halfN = p.Nout >> 1;
    int total = p.M * halfN;
    if (idx >= total) return;
    int row = idx / halfN;
    int col = (idx % halfN) * 2;
    const __half *a0, *a1, *a2, *a3; const float* ad; __half* o;
    resolve_row<MODE>(p, row, a0, a1, a2, a3, ad, o);
    if (!o) return;
    float v0 = (MODE == M_DOWN2) ? 0.f : p.bias[col];
    float v1 = (MODE == M_DOWN2) ? 0.f : p.bias[col + 1];
    if (ad) { v0 += ad[col]; v1 += ad[col + 1]; }
    for (int z = 0; z < nz; z++) {
        const float* q = p.partial + ((size_t)z * p.M + row) * p.Nout + col;
        v0 += q[0]; v1 += q[1];
    }
    *reinterpret_cast<__half2*>(o + col) = __floats2half2_rn(tanhf(v0), tanhf(v1));
}

// ---------------- classifier ----------------
__global__ __launch_bounds__(256) void clf_kernel(const float* __restrict__ clfW,
                                                  const float* __restrict__ clfb,
                                                  float* __restrict__ out) {
    int row = blockIdx.x * 8 + (threadIdx.x >> 5);
    if (row >= BB * NSEQ) return;
    int lane = threadIdx.x & 31;
    const __half2* dn = reinterpret_cast<const __half2*>(g_down + (size_t)row * HH);
    const __half2* up = reinterpret_cast<const __half2*>(g_up   + (size_t)row * HH);
    float s0 = 0.f, s1 = 0.f, s2 = 0.f;
    for (int i = lane; i < 512; i += 32) {
        float2 d = __half22float2(dn[i]);
        float2 u = __half22float2(up[i]);
        int k = 2 * i;
        const float* w  = clfW + (size_t)k * 3;
        const float* w2 = clfW + (size_t)(k + HH) * 3;
        s0 += d.x * w[0] + d.y * w[3] + u.x * w2[0] + u.y * w2[3];
        s1 += d.x * w[1] + d.y * w[4] + u.x * w2[1] + u.y * w2[4];
        s2 += d.x * w[2] + d.y * w[5] + u.x * w2[2] + u.y * w2[5];
    }
    #pragma unroll
    for (int o = 16; o > 0; o >>= 1) {
        s0 += __shfl_xor_sync(0xFFFFFFFFu, s0, o);
        s1 += __shfl_xor_sync(0xFFFFFFFFu, s1, o);
        s2 += __shfl_xor_sync(0xFFFFFFFFu, s2, o);
    }
    if (lane == 0) {
        out[(size_t)row * 3 + 0] = tanhf(s0 + clfb[0]);
        out[(size_t)row * 3 + 1] = tanhf(s1 + clfb[1]);
        out[(size_t)row * 3 + 2] = tanhf(s2 + clfb[2]);
    }
}

// ---------------- host ----------------
extern "C" void kernel_launch(void* const* d_in, const int* in_sizes, int n_in,
                              void* d_out, int out_size) {
    (void)in_sizes; (void)n_in; (void)out_size;
    const int*   x     = (const int*)  d_in[0];
    const int*   cue   = (const int*)  d_in[2];
    const int*   pos   = (const int*)  d_in[4];
    const float* wemb  = (const float*)d_in[6];
    const float* syn   = (const float*)d_in[7];
    const float* leafW = (const float*)d_in[8];
    const float* leafb = (const float*)d_in[9];
    const float* compW = (const float*)d_in[10];
    const float* compb = (const float*)d_in[11];
    const float* grevW = (const float*)d_in[12];
    const float* grevb = (const float*)d_in[13];
    const float* decW  = (const float*)d_in[14];
    const float* decb  = (const float*)d_in[15];
    const float* clfW  = (const float*)d_in[16];
    const float* clfb  = (const float*)d_in[17];
    float* out = (float*)d_out;

    __half *wc, *wd, *wl, *wg;
    float* gp;
    cudaGetSymbolAddress((void**)&wc, g_wcomp);
    cudaGetSymbolAddress((void**)&wd, g_wdec);
    cudaGetSymbolAddress((void**)&wl, g_wleaf);
    cudaGetSymbolAddress((void**)&wg, g_wgrev);
    cudaGetSymbolAddress((void**)&gp, g_partial);

    cudaFuncSetAttribute(hgemm<M_LEAF, false>, cudaFuncAttributeMaxDynamicSharedMemorySize, DSMEM);
    cudaFuncSetAttribute(hgemm<M_UP,   true>,  cudaFuncAttributeMaxDynamicSharedMemorySize, DSMEM);
    cudaFuncSetAttribute(hgemm<M_PRE,  false>, cudaFuncAttributeMaxDynamicSharedMemorySize, DSMEM);
    cudaFuncSetAttribute(hgemm<M_DOWN2, true>, cudaFuncAttributeMaxDynamicSharedMemorySize, DSMEM);
    cudaFuncSetAttribute(hgemm_s<M_UP,    true>, cudaFuncAttributeMaxDynamicSharedMemorySize, DSMEM_S);
    cudaFuncSetAttribute(hgemm_s<M_GREV,  true>, cudaFuncAttributeMaxDynamicSharedMemorySize, DSMEM_S);
    cudaFuncSetAttribute(hgemm_s<M_DOWN2, true>, cudaFuncAttributeMaxDynamicSharedMemorySize, DSMEM_S);

    prep_all<<<1024, 256>>>(compW, decW, leafW, grevW, syn);
    build_leafA<<<(BB * LL + 7) / 8, 256>>>(x, pos, wemb, syn);

    GP base{};
    base.x = x; base.cue = cue; base.leafW = leafW;
    base.node_base = 0; base.node_cnt = 1;
    base.partial = nullptr; base.kcpz = 0;

    auto kslices_for = [](int ctas) -> int {
        if (ctas <= 32) return 8;
        if (ctas <= 64) return 4;
        return 1;
    };

    // leaf
    {
        GP q = base;
        q.W = wl; q.bias = leafb; q.ldw = 1024; q.Nout = 1024;
        q.M = BB * LL; q.Ktot = KP_LG; q.nph = 1;
        q.ph_start[0] = 0; q.ph_start[1] = 1 << 20; q.ph_start[2] = 1 << 20; q.ph_start[3] = 1 << 20;
        hgemm<M_LEAF, false><<<dim3(4, q.M / MT), 512, DSMEM>>>(q);
    }
    // up pass
    for (int lvl = 8; lvl >= 0; lvl--) {
        int cnt = 1 << lvl;
        GP q = base;
        q.W = wc; q.bias = compb; q.ldw = 1024; q.Nout = 1024;
        q.M = BB * cnt; q.Ktot = KP_COMP; q.nph = 2;
        q.node_base = cnt - 1; q.node_cnt = cnt;
        q.ph_start[0] = 0; q.ph_start[1] = 1; q.ph_start[2] = 1 << 20; q.ph_start[3] = 1 << 20;
        if (q.M >= 4096) {
            hgemm<M_UP, true><<<dim3(4, q.M / MT), 512, DSMEM>>>(q);
        } else {
            int gx = 8, gy = q.M / MT_S;
            int ks = kslices_for(gx * gy);
            int nc = q.Ktot / BK;
            if (ks > 1) {
                q.partial = gp; q.kcpz = (nc + ks - 1) / ks;
                hgemm_s<M_UP, true><<<dim3(gx, gy, ks), 256, DSMEM_S>>>(q);
                int total = q.M * (q.Nout / 2);
                reduceK<M_UP><<<(total + 255) / 256, 256>>>(q, ks);
            } else {
                hgemm_s<M_UP, true><<<dim3(gx, gy), 256, DSMEM_S>>>(q);
            }
        }
    }
    // precompute P = syn_l@W + syn_r@W + up@W_up + dec_b  (one big GEMM, all internal nodes)
    {
        GP q = base;
        q.W = wd; q.bias = decb; q.ldw = 2048; q.Nout = 2048;
        q.M = BB * INTN; q.Ktot = KP_PRE; q.nph = 3;
        q.cue = pos;
        q.ph_start[0] = 0; q.ph_start[1] = 1; q.ph_start[2] = 2; q.ph_start[3] = 1 << 20;
        hgemm<M_PRE, false><<<dim3(8, (q.M + MT - 1) / MT), 512, DSMEM>>>(q);
    }
    // grev
    {
        GP q = base;
        q.W = wg; q.bias = grevb; q.ldw = 1024; q.Nout = 1024;
        q.M = BB; q.Ktot = KP_LG; q.nph = 2;
        q.ph_start[0] = 0; q.ph_start[1] = 16; q.ph_start[2] = 1 << 20; q.ph_start[3] = 1 << 20;
        int ks = 8, nc = q.Ktot / BK;
        q.partial = gp; q.kcpz = (nc + ks - 1) / ks;
        hgemm_s<M_GREV, true><<<dim3(8, 1, ks), 256, DSMEM_S>>>(q);
        int total = q.M * (q.Nout / 2);
        reduceK<M_GREV><<<(total + 255) / 256, 256>>>(q, ks);
    }
    // down pass: K=1024 only (down_n), additive row P
    for (int lvl = 0; lvl < 9; lvl++) {
        int cnt = 1 << lvl;
        GP q = base;
        q.W = wd + (size_t)KP_PRE * 2048;   // DOWN weight block
        q.bias = decb; q.ldw = 2048; q.Nout = 2048;
        q.M = BB * cnt; q.Ktot = 1024; q.nph = 1;
        q.node_base = cnt - 1; q.node_cnt = cnt;
        q.ph_start[0] = 0; q.ph_start[1] = 1 << 20; q.ph_start[2] = 1 << 20; q.ph_start[3] = 1 << 20;
        if (q.M >= 4096) {
            hgemm<M_DOWN2, true><<<dim3(8, q.M / MT), 512, DSMEM>>>(q);
        } else {
            int gx = 16, gy = q.M / MT_S;
            int ks = kslices_for(gx * gy);
            int nc = q.Ktot / BK;
            if (ks > 1) {
                q.partial = gp; q.kcpz = (nc + ks - 1) / ks;
                hgemm_s<M_DOWN2, true><<<dim3(gx, gy, ks), 256, DSMEM_S>>>(q);
                int total = q.M * (q.Nout / 2);
                reduceK<M_DOWN2><<<(total + 255) / 256, 256>>>(q, ks);
            } else {
                hgemm_s<M_DOWN2, true><<<dim3(gx, gy), 256, DSMEM_S>>>(q);
            }
        }
    }
    clf_kernel<<<(BB * NSEQ + 7) / 8, 256>>>(clfW, clfb, out);
}

// round 15
// speedup vs baseline: 1.0320x; 1.0320x over previous
#include <cuda_runtime.h>
#include <cuda_fp16.h>
#include <cstdint>
#include <math.h>

#define BB   32
#define NSEQ 1023
#define LL   512
#define HH   1024
#define SHD  50
#define SYNR 128

// ---- big kernel: 512 threads, 16 warps, warp tile 32x64, BK=64, 4 stages ----
#define MT     128
#define NTILE  256
#define BK     64
#define STAGES 4
#define A_STR 72
#define B_STR 264
#define AS_BYTES (MT * A_STR * 2)
#define BS_BYTES (BK * B_STR * 2)
#define STAGE_BYTES (AS_BYTES + BS_BYTES)
#define DSMEM (STAGES * STAGE_BYTES)

// ---- small kernel: 32x128 tile, BK=64, 4 stages ----
#define MT_S    32
#define NTILE_S 128
#define STAGES_S 4
#define BS_STR_S 136
#define AS_BYTES_S (MT_S * A_STR * 2)
#define BS_BYTES_S (BK * BS_STR_S * 2)
#define STAGE_BYTES_S (AS_BYTES_S + BS_BYTES_S)
#define DSMEM_S (STAGES_S * STAGE_BYTES_S)

#define KP_COMP 2112
#define KP_DEC  2176
#define KP_LG   1088

// ---------------- scratch ----------------
__device__ __half g_up   [(size_t)BB * NSEQ * HH];
__device__ __half g_down [(size_t)BB * NSEQ * HH];
__device__ __half g_wcomp[(size_t)KP_COMP * 1024];
__device__ __half g_wdec [(size_t)KP_DEC  * 2048];
__device__ __half g_wleaf[(size_t)KP_LG   * 1024];
__device__ __half g_wgrev[(size_t)KP_LG   * 1024];
__device__ __half g_syn  [(size_t)SYNR * 64];
__device__ __half g_leafA[(size_t)BB * LL * KP_LG];
__device__ float  g_partial[(size_t)8 * 2048 * 2048];

// ---------------- helpers ----------------
__device__ __forceinline__ uint32_t smem_u32(const void* p) {
    uint32_t a;
    asm("{ .reg .u64 t; cvta.to.shared.u64 t, %1; cvt.u32.u64 %0, t; }" : "=r"(a) : "l"(p));
    return a;
}
#define CP_ASYNC16(dst, src) \
    asm volatile("cp.async.cg.shared.global [%0], [%1], 16;" :: "r"(dst), "l"(src))
#define CP_COMMIT() asm volatile("cp.async.commit_group;" ::: "memory")
#define CP_WAIT2()  asm volatile("cp.async.wait_group 2;" ::: "memory")

#define LDSM_X4(R, addr) \
    asm volatile("ldmatrix.sync.aligned.m8n8.x4.shared.b16 {%0,%1,%2,%3}, [%4];" \
        : "=r"((R)[0]), "=r"((R)[1]), "=r"((R)[2]), "=r"((R)[3]) : "r"(addr))
#define LDSM_X4T(R, addr) \
    asm volatile("ldmatrix.sync.aligned.m8n8.x4.trans.shared.b16 {%0,%1,%2,%3}, [%4];" \
        : "=r"((R)[0]), "=r"((R)[1]), "=r"((R)[2]), "=r"((R)[3]) : "r"(addr))

#define MMA16816(c, a, b0, b1) \
    asm volatile("mma.sync.aligned.m16n8k16.row.col.f32.f16.f16.f32 " \
        "{%0,%1,%2,%3}, {%4,%5,%6,%7}, {%8,%9}, {%0,%1,%2,%3};" \
        : "+f"((c)[0]), "+f"((c)[1]), "+f"((c)[2]), "+f"((c)[3]) \
        : "r"((a)[0]), "r"((a)[1]), "r"((a)[2]), "r"((a)[3]), "r"(b0), "r"(b1))

enum { M_LEAF = 0, M_UP, M_GREV, M_DOWN };

struct GP {
    const __half* W;
    const float* bias;
    int ldw, M, Ktot, nph, node_base, node_cnt;
    int ph_start[4];      // in BK-chunk units
    const int *x, *cue;   // M_DOWN: cue slot carries pos
    const float* leafW;
    int Nout, kcpz;
    float* partial;
};

template<int MODE>
__device__ __forceinline__ void resolve_row(const GP& p, int r,
        const __half*& a0, const __half*& a1, const __half*& a2, const __half*& a3,
        const float*& ad, __half*& o) {
    a0 = p.W; a1 = p.W; a2 = p.W; a3 = p.W; ad = nullptr; o = nullptr;
    if (r >= p.M) return;
    if (MODE == M_LEAF) {
        int b = r >> 9, l = r & (LL - 1);
        int w = (LL - 1) + l;
        int c = p.cue[b * NSEQ + w];
        a0 = g_leafA + (size_t)r * KP_LG;
        ad = p.leafW + (size_t)(HH + c) * HH;
        o  = g_up + ((size_t)b * NSEQ + w) * HH;
    } else if (MODE == M_UP) {
        int b = r / p.node_cnt, n = p.node_base + r % p.node_cnt;
        a0 = g_syn + (size_t)p.x[b * NSEQ + n] * 64;
        a1 = g_up + ((size_t)b * NSEQ + 2 * n + 1) * HH;
        o  = g_up + ((size_t)b * NSEQ + n) * HH;
    } else if (MODE == M_GREV) {
        int b = r;
        a0 = g_up + (size_t)b * NSEQ * HH;
        a1 = g_syn + (size_t)p.x[b * NSEQ] * 64;
        o  = g_down + (size_t)b * NSEQ * HH;
    } else {
        int b = r / p.node_cnt, n = p.node_base + r % p.node_cnt;
        int cl = 2 * n + 1, cr = 2 * n + 2;
        const int* pp = p.cue;
        int si_l = (cl >= LL - 1) ? pp[b * LL + cl - (LL - 1)] : p.x[b * NSEQ + cl];
        int si_r = (cr >= LL - 1) ? pp[b * LL + cr - (LL - 1)] : p.x[b * NSEQ + cr];
        a0 = g_syn + (size_t)si_l * 64;
        a1 = g_syn + (size_t)si_r * 64;
        a2 = g_down + ((size_t)b * NSEQ + n) * HH;
        a3 = g_up + ((size_t)b * NSEQ + n) * HH;
        o  = g_down + ((size_t)b * NSEQ + cl) * HH;
    }
}

// ---------------- fused prep kernel ----------------
__device__ __forceinline__ void conv4(__half* dst, const float* src) {
    if (src) {
        float4 v = *reinterpret_cast<const float4*>(src);
        __half2* d = reinterpret_cast<__half2*>(dst);
        d[0] = __floats2half2_rn(v.x, v.y);
        d[1] = __floats2half2_rn(v.z, v.w);
    } else {
        *reinterpret_cast<uint2*>(dst) = make_uint2(0, 0);
    }
}

__global__ void prep_all(const float* __restrict__ compW, const float* __restrict__ decW,
                         const float* __restrict__ leafW, const float* __restrict__ grevW,
                         const float* __restrict__ syn) {
    const size_t S0 = (size_t)KP_COMP * 256;
    const size_t S1 = (size_t)KP_DEC  * 512;
    const size_t S2 = (size_t)KP_LG   * 256;
    const size_t S3 = (size_t)KP_LG   * 256;
    const size_t S4 = (size_t)SYNR * 64;
    const size_t total = S0 + S1 + S2 + S3 + S4;
    for (size_t i = (size_t)blockIdx.x * blockDim.x + threadIdx.x; i < total;
         i += (size_t)gridDim.x * blockDim.x) {
        if (i < S0) {
            int r = (int)(i >> 8), v = (int)(i & 255);
            const float* s;
            if (r < 50) s = compW + (size_t)r * 1024 + v * 4;
            else if (r < 64) s = nullptr;
            else s = compW + (size_t)(50 + r - 64) * 1024 + v * 4;
            conv4(g_wcomp + (size_t)r * 1024 + v * 4, s);
        } else if (i < S0 + S1) {
            size_t j = i - S0;
            int r = (int)(j >> 9), v = (int)(j & 511);
            const float* s;
            if (r < 50) s = decW + (size_t)r * 2048 + v * 4;
            else if (r < 64) s = nullptr;
            else if (r < 114) s = decW + (size_t)(50 + r - 64) * 2048 + v * 4;
            else if (r < 128) s = nullptr;
            else s = decW + (size_t)(100 + r - 128) * 2048 + v * 4;
            conv4(g_wdec + (size_t)r * 2048 + v * 4, s);
        } else if (i < S0 + S1 + S2) {
            size_t j = i - S0 - S1;
            int r = (int)(j >> 8), v = (int)(j & 255);
            const float* s;
            if (r < 1024) s = leafW + (size_t)r * 1024 + v * 4;
            else if (r < 1074) s = leafW + (size_t)(1027 + r - 1024) * 1024 + v * 4;
            else s = nullptr;
            conv4(g_wleaf + (size_t)r * 1024 + v * 4, s);
        } else if (i < S0 + S1 + S2 + S3) {
            size_t j = i - S0 - S1 - S2;
            int r = (int)(j >> 8), v = (int)(j & 255);
            const float* s = (r < 1074) ? grevW + (size_t)r * 1024 + v * 4 : nullptr;
            conv4(g_wgrev + (size_t)r * 1024 + v * 4, s);
        } else {
            size_t j = i - S0 - S1 - S2 - S3;
            int r = (int)(j >> 6), c = (int)(j & 63);
            g_syn[(size_t)r * 64 + c] = (c < SHD) ? __float2half_rn(syn[(size_t)r * SHD + c])
                                                  : __ushort_as_half(0);
        }
    }
}

__global__ __launch_bounds__(256) void build_leafA(const int* __restrict__ x,
                                                   const int* __restrict__ pos,
                                                   const float* __restrict__ wemb,
                                                   const float* __restrict__ syn) {
    int row = blockIdx.x * 8 + (threadIdx.x >> 5);
    if (row >= BB * LL) return;
    int lane = threadIdx.x & 31;
    int b = row >> 9, l = row & (LL - 1);
    int w = (LL - 1) + l;
    int s = x[b * NSEQ + w];
    int pr = pos[b * LL + l];
    const float4* src = reinterpret_cast<const float4*>(wemb + (size_t)s * HH);
    __half* dst = g_leafA + (size_t)row * KP_LG;
    #pragma unroll
    for (int i = 0; i < 8; i++) {
        float4 v = src[lane + i * 32];
        reinterpret_cast<__half2*>(dst)[(lane + i * 32) * 2]     = __floats2half2_rn(v.x, v.y);
        reinterpret_cast<__half2*>(dst)[(lane + i * 32) * 2 + 1] = __floats2half2_rn(v.z, v.w);
    }
    {
        int c0 = lane * 2;
        float f0 = (c0     < SHD) ? syn[(size_t)pr * SHD + c0]     : 0.f;
        float f1 = (c0 + 1 < SHD) ? syn[(size_t)pr * SHD + c0 + 1] : 0.f;
        reinterpret_cast<__half2*>(dst + 1024)[lane] = __floats2half2_rn(f0, f1);
    }
}

// ---------------- big fp16 GEMM: BK=64, 4 stages ----------------
template<int MODE, bool DOTANH>
__global__ __launch_bounds__(512) void hgemm(GP p) {
    __shared__ const __half* sAp[4][MT];
    __shared__ __half* sO[MT];
    __shared__ const float* sAdd[MT];
    extern __shared__ __align__(16) char dynraw[];

    const int tid = threadIdx.x;
    const int wid = tid >> 5;
    const int lane = tid & 31;
    const int rbase = blockIdx.y * MT;
    const int nblk = blockIdx.x * NTILE;

    if (tid < MT) {
        const __half *a0, *a1, *a2, *a3; const float* ad; __half* o;
        resolve_row<MODE>(p, rbase + tid, a0, a1, a2, a3, ad, o);
        sAp[0][tid] = a0; sAp[1][tid] = a1; sAp[2][tid] = a2; sAp[3][tid] = a3;
        sO[tid] = o; sAdd[tid] = ad;
    }
    __syncthreads();

    const int nc = p.Ktot / BK;
    const uint32_t dynB = smem_u32(dynraw);

    auto prefetch = [&](int c, int stage) {
        const uint32_t asB = dynB + stage * STAGE_BYTES;
        const uint32_t bsB = asB + AS_BYTES;
        int phidx = 0;
        #pragma unroll
        for (int q = 1; q < 4; q++) if (q < p.nph && c >= p.ph_start[q]) phidx = q;
        const int kloc = (c - p.ph_start[phidx]) * BK;
        #pragma unroll
        for (int i = 0; i < 2; i++) {
            int lin = i * 512 + tid;
            int row = lin >> 3, seg = lin & 7;
            CP_ASYNC16(asB + (row * A_STR + seg * 8) * 2, sAp[phidx][row] + kloc + seg * 8);
        }
        const __half* wsrc = p.W + (size_t)(c * BK) * p.ldw + nblk;
        #pragma unroll
        for (int i = 0; i < 4; i++) {
            int lin = i * 512 + tid;
            int row = lin >> 5, seg = lin & 31;
            CP_ASYNC16(bsB + (row * B_STR + seg * 8) * 2, wsrc + (size_t)row * p.ldw + seg * 8);
        }
    };

    const int warp_m = wid & 3;
    const int warp_n = wid >> 2;
    const uint32_t aLane = ((warp_m * 32 + (lane & 15)) * A_STR + (lane >> 4) * 8) * 2;
    const uint32_t bLane = ((lane & 15) * B_STR + warp_n * 64 + (lane >> 4) * 8) * 2;

    float cacc[2][8][4];
    #pragma unroll
    for (int i = 0; i < 2; i++)
        #pragma unroll
        for (int j = 0; j < 8; j++)
            #pragma unroll
            for (int e = 0; e < 4; e++) cacc[i][j][e] = 0.f;

    #pragma unroll
    for (int s = 0; s < STAGES - 1; s++) {
        if (s < nc) prefetch(s, s);
        CP_COMMIT();
    }

    for (int c = 0; c < nc; c++) {
        CP_WAIT2();
        __syncthreads();
        const int stage = c & (STAGES - 1);
        const uint32_t asB = dynB + stage * STAGE_BYTES;
        const uint32_t bsB = asB + AS_BYTES;
        #pragma unroll
        for (int kk = 0; kk < 4; kk++) {
            uint32_t af[2][4], bf[4][4];
            #pragma unroll
            for (int mf = 0; mf < 2; mf++)
                LDSM_X4(af[mf], asB + aLane + (mf * 16 * A_STR + kk * 16) * 2);
            #pragma unroll
            for (int nfp = 0; nfp < 4; nfp++)
                LDSM_X4T(bf[nfp], bsB + bLane + (kk * 16 * B_STR + nfp * 16) * 2);
            #pragma unroll
            for (int mf = 0; mf < 2; mf++)
                #pragma unroll
                for (int nfp = 0; nfp < 4; nfp++) {
                    MMA16816(cacc[mf][nfp * 2],     af[mf], bf[nfp][0], bf[nfp][1]);
                    MMA16816(cacc[mf][nfp * 2 + 1], af[mf], bf[nfp][2], bf[nfp][3]);
                }
        }
        int pc = c + STAGES - 1;
        if (pc < nc) prefetch(pc, pc & (STAGES - 1));
        CP_COMMIT();
    }

    {
        const int g = lane >> 2, t = lane & 3;
        #pragma unroll
        for (int mf = 0; mf < 2; mf++) {
            const int tr1 = warp_m * 32 + mf * 16 + g;
            const int tr2 = tr1 + 8;
            __half* o1 = sO[tr1];
            __half* o2 = sO[tr2];
            const float* ad1 = sAdd[tr1];
            const float* ad2 = sAdd[tr2];
            #pragma unroll
            for (int nf = 0; nf < 8; nf++) {
                const int col0 = nblk + warp_n * 64 + nf * 8 + t * 2;
                const float b0 = p.bias[col0], b1 = p.bias[col0 + 1];
                const float* cc = cacc[mf][nf];
                if (o1) {
                    float v0 = cc[0] + b0, v1 = cc[1] + b1;
                    if (MODE == M_LEAF && ad1) { v0 += ad1[col0]; v1 += ad1[col0 + 1]; }
                    if (DOTANH) { v0 = tanhf(v0); v1 = tanhf(v1); }
                    *reinterpret_cast<__half2*>(o1 + col0) = __floats2half2_rn(v0, v1);
                }
                if (o2) {
                    float v0 = cc[2] + b0, v1 = cc[3] + b1;
                    if (MODE == M_LEAF && ad2) { v0 += ad2[col0]; v1 += ad2[col0 + 1]; }
                    if (DOTANH) { v0 = tanhf(v0); v1 = tanhf(v1); }
                    *reinterpret_cast<__half2*>(o2 + col0) = __floats2half2_rn(v0, v1);
                }
            }
        }
    }
}

// ---------------- small-M fp16 GEMM: BK=64, 4 stages, single barrier/chunk ----------------
template<int MODE, bool DOTANH>
__global__ __launch_bounds__(256, 2) void hgemm_s(GP p) {
    __shared__ const __half* sAp[4][MT_S];
    __shared__ __half* sO[MT_S];
    extern __shared__ __align__(16) char dynraw[];

    const int tid = threadIdx.x;
    const int wid = tid >> 5;
    const int lane = tid & 31;
    const int rbase = blockIdx.y * MT_S;
    const int nblk = blockIdx.x * NTILE_S;

    if (tid < MT_S) {
        const __half *a0, *a1, *a2, *a3; const float* ad; __half* o;
        resolve_row<MODE>(p, rbase + tid, a0, a1, a2, a3, ad, o);
        sAp[0][tid] = a0; sAp[1][tid] = a1; sAp[2][tid] = a2; sAp[3][tid] = a3;
        sO[tid] = o;
    }
    __syncthreads();

    const int nc = p.Ktot / BK;
    int c0 = 0, ncc = nc;
    if (p.partial) {
        c0 = blockIdx.z * p.kcpz;
        ncc = nc - c0;
        if (ncc > p.kcpz) ncc = p.kcpz;
        if (ncc < 0) ncc = 0;
    }
    const uint32_t dynB = smem_u32(dynraw);

    auto prefetch = [&](int c, int stage) {
        const uint32_t asB = dynB + stage * STAGE_BYTES_S;
        const uint32_t bsB = asB + AS_BYTES_S;
        int phidx = 0;
        #pragma unroll
        for (int q = 1; q < 4; q++) if (q < p.nph && c >= p.ph_start[q]) phidx = q;
        const int kloc = (c - p.ph_start[phidx]) * BK;
        {
            int row = tid >> 3, seg = tid & 7;
            CP_ASYNC16(asB + (row * A_STR + seg * 8) * 2, sAp[phidx][row] + kloc + seg * 8);
        }
        const __half* wsrc = p.W + (size_t)(c * BK) * p.ldw + nblk;
        #pragma unroll
        for (int i = 0; i < 4; i++) {
            int lin = i * 256 + tid;
            int row = lin >> 4, seg = lin & 15;
            CP_ASYNC16(bsB + (row * BS_STR_S + seg * 8) * 2, wsrc + (size_t)row * p.ldw + seg * 8);
        }
    };

    const uint32_t aLane = ((lane & 15) * A_STR + (lane >> 4) * 8) * 2;
    const uint32_t bLane = ((lane & 15) * BS_STR_S + wid * 16 + (lane >> 4) * 8) * 2;

    float cacc[2][2][4];
    #pragma unroll
    for (int i = 0; i < 2; i++)
        #pragma unroll
        for (int j = 0; j < 2; j++)
            #pragma unroll
            for (int e = 0; e < 4; e++) cacc[i][j][e] = 0.f;

    #pragma unroll
    for (int s = 0; s < STAGES_S - 1; s++) {
        if (s < ncc) prefetch(c0 + s, s);
        CP_COMMIT();
    }

    for (int cc = 0; cc < ncc; cc++) {
        CP_WAIT2();
        __syncthreads();
        const int stage = cc & (STAGES_S - 1);
        const uint32_t asB = dynB + stage * STAGE_BYTES_S;
        const uint32_t bsB = asB + AS_BYTES_S;
        #pragma unroll
        for (int kk = 0; kk < 4; kk++) {
            uint32_t af[2][4], bf[4];
            #pragma unroll
            for (int mf = 0; mf < 2; mf++)
                LDSM_X4(af[mf], asB + aLane + (mf * 16 * A_STR + kk * 16) * 2);
            LDSM_X4T(bf, bsB + bLane + (kk * 16 * BS_STR_S) * 2);
            #pragma unroll
            for (int mf = 0; mf < 2; mf++) {
                MMA16816(cacc[mf][0], af[mf], bf[0], bf[1]);
                MMA16816(cacc[mf][1], af[mf], bf[2], bf[3]);
            }
        }
        int pcc = cc + STAGES_S - 1;
        if (pcc < ncc) prefetch(c0 + pcc, pcc & (STAGES_S - 1));
        CP_COMMIT();
    }

    {
        const int g = lane >> 2, t = lane & 3;
        if (p.partial) {
            float* base = p.partial + (size_t)blockIdx.z * p.M * p.Nout;
            #pragma unroll
            for (int mf = 0; mf < 2; mf++) {
                const int r1 = rbase + mf * 16 + g;
                const int r2 = r1 + 8;
                #pragma unroll
                for (int nf = 0; nf < 2; nf++) {
                    const int col0 = nblk + wid * 16 + nf * 8 + t * 2;
                    const float* cc = cacc[mf][nf];
                    if (r1 < p.M)
                        *reinterpret_cast<float2*>(base + (size_t)r1 * p.Nout + col0) =
                            make_float2(cc[0], cc[1]);
                    if (r2 < p.M)
                        *reinterpret_cast<float2*>(base + (size_t)r2 * p.Nout + col0) =
                            make_float2(cc[2], cc[3]);
                }
            }
        } else {
            #pragma unroll
            for (int mf = 0; mf < 2; mf++) {
                const int tr1 = mf * 16 + g;
                const int tr2 = tr1 + 8;
                __half* o1 = sO[tr1];
                __half* o2 = sO[tr2];
                #pragma unroll
                for (int nf = 0; nf < 2; nf++) {
                    const int col0 = nblk + wid * 16 + nf * 8 + t * 2;
                    const float b0 = p.bias[col0], b1 = p.bias[col0 + 1];
                    const float* cc = cacc[mf][nf];
                    if (o1) {
                        float v0 = cc[0] + b0, v1 = cc[1] + b1;
                        if (DOTANH) { v0 = tanhf(v0); v1 = tanhf(v1); }
                        *reinterpret_cast<__half2*>(o1 + col0) = __floats2half2_rn(v0, v1);
                    }
                    if (o2) {
                        float v0 = cc[2] + b0, v1 = cc[3] + b1;
                        if (DOTANH) { v0 = tanhf(v0); v1 = tanhf(v1); }
                        *reinterpret_cast<__half2*>(o2 + col0) = __floats2half2_rn(v0, v1);
                    }
                }
            }
        }
    }
}

// ---------------- split-K reduction ----------------
template<int MODE>
__global__ __launch_bounds__(256) void reduceK(GP p, int nz) {
    int idx = blockIdx.x * 256 + threadIdx.x;
    int halfN = p.Nout >> 1;
    int total = p.M * halfN;
    if (idx >= total) return;
    int row = idx / halfN;
    int col = (idx % halfN) * 2;
    const __half *a0, *a1, *a2, *a3; const float* ad; __half* o;
    resolve_row<MODE>(p, row, a0, a1, a2, a3, ad, o);
    if (!o) return;
    float v0 = p.bias[col], v1 = p.bias[col + 1];
    for (int z = 0; z < nz; z++) {
        const float* q = p.partial + ((size_t)z * p.M + row) * p.Nout + col;
        v0 += q[0]; v1 += q[1];
    }
    *reinterpret_cast<__half2*>(o + col) = __floats2half2_rn(tanhf(v0), tanhf(v1));
}

// ---------------- classifier ----------------
__global__ __launch_bounds__(256) void clf_kernel(const float* __restrict__ clfW,
                                                  const float* __restrict__ clfb,
                                                  float* __restrict__ out) {
    int row = blockIdx.x * 8 + (threadIdx.x >> 5);
    if (row >= BB * NSEQ) return;
    int lane = threadIdx.x & 31;
    const __half2* dn = reinterpret_cast<const __half2*>(g_down + (size_t)row * HH);
    const __half2* up = reinterpret_cast<const __half2*>(g_up   + (size_t)row * HH);
    float s0 = 0.f, s1 = 0.f, s2 = 0.f;
    for (int i = lane; i < 512; i += 32) {
        float2 d = __half22float2(dn[i]);
        float2 u = __half22float2(up[i]);
        int k = 2 * i;
        const float* w  = clfW + (size_t)k * 3;
        const float* w2 = clfW + (size_t)(k + HH) * 3;
        s0 += d.x * w[0] + d.y * w[3] + u.x * w2[0] + u.y * w2[3];
        s1 += d.x * w[1] + d.y * w[4] + u.x * w2[1] + u.y * w2[4];
        s2 += d.x * w[2] + d.y * w[5] + u.x * w2[2] + u.y * w2[5];
    }
    #pragma unroll
    for (int o = 16; o > 0; o >>= 1) {
        s0 += __shfl_xor_sync(0xFFFFFFFFu, s0, o);
        s1 += __shfl_xor_sync(0xFFFFFFFFu, s1, o);
        s2 += __shfl_xor_sync(0xFFFFFFFFu, s2, o);
    }
    if (lane == 0) {
        out[(size_t)row * 3 + 0] = tanhf(s0 + clfb[0]);
        out[(size_t)row * 3 + 1] = tanhf(s1 + clfb[1]);
        out[(size_t)row * 3 + 2] = tanhf(s2 + clfb[2]);
    }
}

// ---------------- host ----------------
extern "C" void kernel_launch(void* const* d_in, const int* in_sizes, int n_in,
                              void* d_out, int out_size) {
    (void)in_sizes; (void)n_in; (void)out_size;
    const int*   x     = (const int*)  d_in[0];
    const int*   cue   = (const int*)  d_in[2];
    const int*   pos   = (const int*)  d_in[4];
    const float* wemb  = (const float*)d_in[6];
    const float* syn   = (const float*)d_in[7];
    const float* leafW = (const float*)d_in[8];
    const float* leafb = (const float*)d_in[9];
    const float* compW = (const float*)d_in[10];
    const float* compb = (const float*)d_in[11];
    const float* grevW = (const float*)d_in[12];
    const float* grevb = (const float*)d_in[13];
    const float* decW  = (const float*)d_in[14];
    const float* decb  = (const float*)d_in[15];
    const float* clfW  = (const float*)d_in[16];
    const float* clfb  = (const float*)d_in[17];
    float* out = (float*)d_out;

    __half *wc, *wd, *wl, *wg;
    float* gp;
    cudaGetSymbolAddress((void**)&wc, g_wcomp);
    cudaGetSymbolAddress((void**)&wd, g_wdec);
    cudaGetSymbolAddress((void**)&wl, g_wleaf);
    cudaGetSymbolAddress((void**)&wg, g_wgrev);
    cudaGetSymbolAddress((void**)&gp, g_partial);

    cudaFuncSetAttribute(hgemm<M_LEAF, false>, cudaFuncAttributeMaxDynamicSharedMemorySize, DSMEM);
    cudaFuncSetAttribute(hgemm<M_UP,   true>,  cudaFuncAttributeMaxDynamicSharedMemorySize, DSMEM);
    cudaFuncSetAttribute(hgemm<M_DOWN, true>,  cudaFuncAttributeMaxDynamicSharedMemorySize, DSMEM);
    cudaFuncSetAttribute(hgemm_s<M_UP,   true>, cudaFuncAttributeMaxDynamicSharedMemorySize, DSMEM_S);
    cudaFuncSetAttribute(hgemm_s<M_GREV, true>, cudaFuncAttributeMaxDynamicSharedMemorySize, DSMEM_S);
    cudaFuncSetAttribute(hgemm_s<M_DOWN, true>, cudaFuncAttributeMaxDynamicSharedMemorySize, DSMEM_S);

    prep_all<<<1024, 256>>>(compW, decW, leafW, grevW, syn);
    build_leafA<<<(BB * LL + 7) / 8, 256>>>(x, pos, wemb, syn);

    GP base{};
    base.x = x; base.cue = cue; base.leafW = leafW;
    base.node_base = 0; base.node_cnt = 1;
    base.partial = nullptr; base.kcpz = 0;

    auto kslices_for = [](int ctas) -> int {
        if (ctas <= 32) return 8;
        if (ctas <= 64) return 4;
        return 1;
    };

    // leaf: K=1088 -> 17 chunks, 1 phase
    {
        GP q = base;
        q.W = wl; q.bias = leafb; q.ldw = 1024; q.Nout = 1024;
        q.M = BB * LL; q.Ktot = KP_LG; q.nph = 1;
        q.ph_start[0] = 0; q.ph_start[1] = 1 << 20; q.ph_start[2] = 1 << 20; q.ph_start[3] = 1 << 20;
        hgemm<M_LEAF, false><<<dim3(4, q.M / MT), 512, DSMEM>>>(q);
    }
    // up pass: syn = chunk 0, children = chunks 1..32
    for (int lvl = 8; lvl >= 0; lvl--) {
        int cnt = 1 << lvl;
        GP q = base;
        q.W = wc; q.bias = compb; q.ldw = 1024; q.Nout = 1024;
        q.M = BB * cnt; q.Ktot = KP_COMP; q.nph = 2;
        q.node_base = cnt - 1; q.node_cnt = cnt;
        q.ph_start[0] = 0; q.ph_start[1] = 1; q.ph_start[2] = 1 << 20; q.ph_start[3] = 1 << 20;
        if (q.M >= 4096) {
            hgemm<M_UP, true><<<dim3(4, q.M / MT), 512, DSMEM>>>(q);
        } else {
            int gx = 8, gy = q.M / MT_S;
            int ks = kslices_for(gx * gy);
            int nc = q.Ktot / BK;
            if (ks > 1) {
                q.partial = gp; q.kcpz = (nc + ks - 1) / ks;
                hgemm_s<M_UP, true><<<dim3(gx, gy, ks), 256, DSMEM_S>>>(q);
                int total = q.M * (q.Nout / 2);
                reduceK<M_UP><<<(total + 255) / 256, 256>>>(q, ks);
            } else {
                hgemm_s<M_UP, true><<<dim3(gx, gy), 256, DSMEM_S>>>(q);
            }
        }
    }
    // grev: up-root = chunks 0..15, syn = chunk 16
    {
        GP q = base;
        q.W = wg; q.bias = grevb; q.ldw = 1024; q.Nout = 1024;
        q.M = BB; q.Ktot = KP_LG; q.nph = 2;
        q.ph_start[0] = 0; q.ph_start[1] = 16; q.ph_start[2] = 1 << 20; q.ph_start[3] = 1 << 20;
        int ks = 8, nc = q.Ktot / BK;
        q.partial = gp; q.kcpz = (nc + ks - 1) / ks;
        hgemm_s<M_GREV, true><<<dim3(8, 1, ks), 256, DSMEM_S>>>(q);
        int total = q.M * (q.Nout / 2);
        reduceK<M_GREV><<<(total + 255) / 256, 256>>>(q, ks);
    }
    // down pass: syn_l=0, syn_r=1, down=2..17, up=18..33
    for (int lvl = 0; lvl < 9; lvl++) {
        int cnt = 1 << lvl;
        GP q = base;
        q.W = wd; q.bias = decb; q.ldw = 2048; q.Nout = 2048;
        q.M = BB * cnt; q.Ktot = KP_DEC; q.nph = 4;
        q.node_base = cnt - 1; q.node_cnt = cnt;
        q.cue = pos;
        q.ph_start[0] = 0; q.ph_start[1] = 1; q.ph_start[2] = 2; q.ph_start[3] = 18;
        if (q.M >= 4096) {
            hgemm<M_DOWN, true><<<dim3(8, q.M / MT), 512, DSMEM>>>(q);
        } else {
            int gx = 16, gy = q.M / MT_S;
            int ks = kslices_for(gx * gy);
            int nc = q.Ktot / BK;
            if (ks > 1) {
                q.partial = gp; q.kcpz = (nc + ks - 1) / ks;
                hgemm_s<M_DOWN, true><<<dim3(gx, gy, ks), 256, DSMEM_S>>>(q);
                int total = q.M * (q.Nout / 2);
                reduceK<M_DOWN><<<(total + 255) / 256, 256>>>(q, ks);
            } else {
                hgemm_s<M_DOWN, true><<<dim3(gx, gy), 256, DSMEM_S>>>(q);
            }
        }
    }
    clf_kernel<<<(BB * NSEQ + 7) / 8, 256>>>(clfW, clfb, out);
}

// round 16
// speedup vs baseline: 1.1066x; 1.0723x over previous
#include <cuda_runtime.h>
#include <cuda_fp16.h>
#include <cstdint>
#include <math.h>

#define BB   32
#define NSEQ 1023
#define LL   512
#define HH   1024
#define SHD  50
#define SYNR 128

// ---- big kernel: 256 threads, 8 warps, CTA 128x128, warp 64x32, BK=64, 3 stages, 2 CTA/SM ----
#define MT     128
#define NTILE  128
#define BK     64
#define STAGES 3
#define A_STR 72
#define B_STR 136
#define AS_BYTES (MT * A_STR * 2)       /* 18432 */
#define BS_BYTES (BK * B_STR * 2)       /* 17408 */
#define STAGE_BYTES (AS_BYTES + BS_BYTES)
#define DSMEM (STAGES * STAGE_BYTES)    /* 107520 -> 2 CTAs/SM */

// ---- small kernel: 32x128 tile, BK=64, 4 stages ----
#define MT_S    32
#define NTILE_S 128
#define STAGES_S 4
#define BS_STR_S 136
#define AS_BYTES_S (MT_S * A_STR * 2)
#define BS_BYTES_S (BK * BS_STR_S * 2)
#define STAGE_BYTES_S (AS_BYTES_S + BS_BYTES_S)
#define DSMEM_S (STAGES_S * STAGE_BYTES_S)

#define KP_COMP 2112
#define KP_DEC  2176
#define KP_LG   1088

// ---------------- scratch ----------------
__device__ __half g_up   [(size_t)BB * NSEQ * HH];
__device__ __half g_down [(size_t)BB * NSEQ * HH];
__device__ __half g_wcomp[(size_t)KP_COMP * 1024];
__device__ __half g_wdec [(size_t)KP_DEC  * 2048];
__device__ __half g_wleaf[(size_t)KP_LG   * 1024];
__device__ __half g_wgrev[(size_t)KP_LG   * 1024];
__device__ __half g_syn  [(size_t)SYNR * 64];
__device__ __half g_leafA[(size_t)BB * LL * KP_LG];
__device__ float  g_partial[(size_t)8 * 2048 * 2048];

// ---------------- helpers ----------------
__device__ __forceinline__ uint32_t smem_u32(const void* p) {
    uint32_t a;
    asm("{ .reg .u64 t; cvta.to.shared.u64 t, %1; cvt.u32.u64 %0, t; }" : "=r"(a) : "l"(p));
    return a;
}
#define CP_ASYNC16(dst, src) \
    asm volatile("cp.async.cg.shared.global [%0], [%1], 16;" :: "r"(dst), "l"(src))
#define CP_COMMIT() asm volatile("cp.async.commit_group;" ::: "memory")
#define CP_WAIT1()  asm volatile("cp.async.wait_group 1;" ::: "memory")
#define CP_WAIT2()  asm volatile("cp.async.wait_group 2;" ::: "memory")

#define LDSM_X4(R, addr) \
    asm volatile("ldmatrix.sync.aligned.m8n8.x4.shared.b16 {%0,%1,%2,%3}, [%4];" \
        : "=r"((R)[0]), "=r"((R)[1]), "=r"((R)[2]), "=r"((R)[3]) : "r"(addr))
#define LDSM_X4T(R, addr) \
    asm volatile("ldmatrix.sync.aligned.m8n8.x4.trans.shared.b16 {%0,%1,%2,%3}, [%4];" \
        : "=r"((R)[0]), "=r"((R)[1]), "=r"((R)[2]), "=r"((R)[3]) : "r"(addr))

#define MMA16816(c, a, b0, b1) \
    asm volatile("mma.sync.aligned.m16n8k16.row.col.f32.f16.f16.f32 " \
        "{%0,%1,%2,%3}, {%4,%5,%6,%7}, {%8,%9}, {%0,%1,%2,%3};" \
        : "+f"((c)[0]), "+f"((c)[1]), "+f"((c)[2]), "+f"((c)[3]) \
        : "r"((a)[0]), "r"((a)[1]), "r"((a)[2]), "r"((a)[3]), "r"(b0), "r"(b1))

enum { M_LEAF = 0, M_UP, M_GREV, M_DOWN };

struct GP {
    const __half* W;
    const float* bias;
    int ldw, M, Ktot, nph, node_base, node_cnt;
    int ph_start[4];      // in BK-chunk units
    const int *x, *cue;   // M_DOWN: cue slot carries pos
    const float* leafW;
    int Nout, kcpz;
    float* partial;
};

template<int MODE>
__device__ __forceinline__ void resolve_row(const GP& p, int r,
        const __half*& a0, const __half*& a1, const __half*& a2, const __half*& a3,
        const float*& ad, __half*& o) {
    a0 = p.W; a1 = p.W; a2 = p.W; a3 = p.W; ad = nullptr; o = nullptr;
    if (r >= p.M) return;
    if (MODE == M_LEAF) {
        int b = r >> 9, l = r & (LL - 1);
        int w = (LL - 1) + l;
        int c = p.cue[b * NSEQ + w];
        a0 = g_leafA + (size_t)r * KP_LG;
        ad = p.leafW + (size_t)(HH + c) * HH;
        o  = g_up + ((size_t)b * NSEQ + w) * HH;
    } else if (MODE == M_UP) {
        int b = r / p.node_cnt, n = p.node_base + r % p.node_cnt;
        a0 = g_syn + (size_t)p.x[b * NSEQ + n] * 64;
        a1 = g_up + ((size_t)b * NSEQ + 2 * n + 1) * HH;
        o  = g_up + ((size_t)b * NSEQ + n) * HH;
    } else if (MODE == M_GREV) {
        int b = r;
        a0 = g_up + (size_t)b * NSEQ * HH;
        a1 = g_syn + (size_t)p.x[b * NSEQ] * 64;
        o  = g_down + (size_t)b * NSEQ * HH;
    } else {
        int b = r / p.node_cnt, n = p.node_base + r % p.node_cnt;
        int cl = 2 * n + 1, cr = 2 * n + 2;
        const int* pp = p.cue;
        int si_l = (cl >= LL - 1) ? pp[b * LL + cl - (LL - 1)] : p.x[b * NSEQ + cl];
        int si_r = (cr >= LL - 1) ? pp[b * LL + cr - (LL - 1)] : p.x[b * NSEQ + cr];
        a0 = g_syn + (size_t)si_l * 64;
        a1 = g_syn + (size_t)si_r * 64;
        a2 = g_down + ((size_t)b * NSEQ + n) * HH;
        a3 = g_up + ((size_t)b * NSEQ + n) * HH;
        o  = g_down + ((size_t)b * NSEQ + cl) * HH;
    }
}

// ---------------- fused prep kernel ----------------
__device__ __forceinline__ void conv4(__half* dst, const float* src) {
    if (src) {
        float4 v = *reinterpret_cast<const float4*>(src);
        __half2* d = reinterpret_cast<__half2*>(dst);
        d[0] = __floats2half2_rn(v.x, v.y);
        d[1] = __floats2half2_rn(v.z, v.w);
    } else {
        *reinterpret_cast<uint2*>(dst) = make_uint2(0, 0);
    }
}

__global__ void prep_all(const float* __restrict__ compW, const float* __restrict__ decW,
                         const float* __restrict__ leafW, const float* __restrict__ grevW,
                         const float* __restrict__ syn) {
    const size_t S0 = (size_t)KP_COMP * 256;
    const size_t S1 = (size_t)KP_DEC  * 512;
    const size_t S2 = (size_t)KP_LG   * 256;
    const size_t S3 = (size_t)KP_LG   * 256;
    const size_t S4 = (size_t)SYNR * 64;
    const size_t total = S0 + S1 + S2 + S3 + S4;
    for (size_t i = (size_t)blockIdx.x * blockDim.x + threadIdx.x; i < total;
         i += (size_t)gridDim.x * blockDim.x) {
        if (i < S0) {
            int r = (int)(i >> 8), v = (int)(i & 255);
            const float* s;
            if (r < 50) s = compW + (size_t)r * 1024 + v * 4;
            else if (r < 64) s = nullptr;
            else s = compW + (size_t)(50 + r - 64) * 1024 + v * 4;
            conv4(g_wcomp + (size_t)r * 1024 + v * 4, s);
        } else if (i < S0 + S1) {
            size_t j = i - S0;
            int r = (int)(j >> 9), v = (int)(j & 511);
            const float* s;
            if (r < 50) s = decW + (size_t)r * 2048 + v * 4;
            else if (r < 64) s = nullptr;
            else if (r < 114) s = decW + (size_t)(50 + r - 64) * 2048 + v * 4;
            else if (r < 128) s = nullptr;
            else s = decW + (size_t)(100 + r - 128) * 2048 + v * 4;
            conv4(g_wdec + (size_t)r * 2048 + v * 4, s);
        } else if (i < S0 + S1 + S2) {
            size_t j = i - S0 - S1;
            int r = (int)(j >> 8), v = (int)(j & 255);
            const float* s;
            if (r < 1024) s = leafW + (size_t)r * 1024 + v * 4;
            else if (r < 1074) s = leafW + (size_t)(1027 + r - 1024) * 1024 + v * 4;
            else s = nullptr;
            conv4(g_wleaf + (size_t)r * 1024 + v * 4, s);
        } else if (i < S0 + S1 + S2 + S3) {
            size_t j = i - S0 - S1 - S2;
            int r = (int)(j >> 8), v = (int)(j & 255);
            const float* s = (r < 1074) ? grevW + (size_t)r * 1024 + v * 4 : nullptr;
            conv4(g_wgrev + (size_t)r * 1024 + v * 4, s);
        } else {
            size_t j = i - S0 - S1 - S2 - S3;
            int r = (int)(j >> 6), c = (int)(j & 63);
            g_syn[(size_t)r * 64 + c] = (c < SHD) ? __float2half_rn(syn[(size_t)r * SHD + c])
                                                  : __ushort_as_half(0);
        }
    }
}

__global__ __launch_bounds__(256) void build_leafA(const int* __restrict__ x,
                                                   const int* __restrict__ pos,
                                                   const float* __restrict__ wemb,
                                                   const float* __restrict__ syn) {
    int row = blockIdx.x * 8 + (threadIdx.x >> 5);
    if (row >= BB * LL) return;
    int lane = threadIdx.x & 31;
    int b = row >> 9, l = row & (LL - 1);
    int w = (LL - 1) + l;
    int s = x[b * NSEQ + w];
    int pr = pos[b * LL + l];
    const float4* src = reinterpret_cast<const float4*>(wemb + (size_t)s * HH);
    __half* dst = g_leafA + (size_t)row * KP_LG;
    #pragma unroll
    for (int i = 0; i < 8; i++) {
        float4 v = src[lane + i * 32];
        reinterpret_cast<__half2*>(dst)[(lane + i * 32) * 2]     = __floats2half2_rn(v.x, v.y);
        reinterpret_cast<__half2*>(dst)[(lane + i * 32) * 2 + 1] = __floats2half2_rn(v.z, v.w);
    }
    {
        int c0 = lane * 2;
        float f0 = (c0     < SHD) ? syn[(size_t)pr * SHD + c0]     : 0.f;
        float f1 = (c0 + 1 < SHD) ? syn[(size_t)pr * SHD + c0 + 1] : 0.f;
        reinterpret_cast<__half2*>(dst + 1024)[lane] = __floats2half2_rn(f0, f1);
    }
}

// ---------------- big fp16 GEMM: 128x128 tile, 3 stages, 2 CTA/SM ----------------
template<int MODE, bool DOTANH>
__global__ __launch_bounds__(256, 2) void hgemm(GP p) {
    __shared__ const __half* sAp[4][MT];
    __shared__ __half* sO[MT];
    __shared__ const float* sAdd[MT];
    extern __shared__ __align__(16) char dynraw[];

    const int tid = threadIdx.x;
    const int wid = tid >> 5;
    const int lane = tid & 31;
    const int rbase = blockIdx.y * MT;
    const int nblk = blockIdx.x * NTILE;

    if (tid < MT) {
        const __half *a0, *a1, *a2, *a3; const float* ad; __half* o;
        resolve_row<MODE>(p, rbase + tid, a0, a1, a2, a3, ad, o);
        sAp[0][tid] = a0; sAp[1][tid] = a1; sAp[2][tid] = a2; sAp[3][tid] = a3;
        sO[tid] = o; sAdd[tid] = ad;
    }
    __syncthreads();

    const int nc = p.Ktot / BK;
    const uint32_t dynB = smem_u32(dynraw);

    auto prefetch = [&](int c, int stage) {
        const uint32_t asB = dynB + stage * STAGE_BYTES;
        const uint32_t bsB = asB + AS_BYTES;
        int phidx = 0;
        #pragma unroll
        for (int q = 1; q < 4; q++) if (q < p.nph && c >= p.ph_start[q]) phidx = q;
        const int kloc = (c - p.ph_start[phidx]) * BK;
        // A: 128 rows x 8 segs = 1024 transfers = 4/thread
        #pragma unroll
        for (int i = 0; i < 4; i++) {
            int lin = i * 256 + tid;
            int row = lin >> 3, seg = lin & 7;
            CP_ASYNC16(asB + (row * A_STR + seg * 8) * 2, sAp[phidx][row] + kloc + seg * 8);
        }
        // B: 64 rows x 16 segs = 1024 transfers = 4/thread
        const __half* wsrc = p.W + (size_t)(c * BK) * p.ldw + nblk;
        #pragma unroll
        for (int i = 0; i < 4; i++) {
            int lin = i * 256 + tid;
            int row = lin >> 4, seg = lin & 15;
            CP_ASYNC16(bsB + (row * B_STR + seg * 8) * 2, wsrc + (size_t)row * p.ldw + seg * 8);
        }
    };

    const int warp_m = wid & 1;        // 2 M-groups of 64 rows
    const int warp_n = wid >> 1;       // 4 N-groups of 32 cols
    const uint32_t aLane = ((warp_m * 64 + (lane & 15)) * A_STR + (lane >> 4) * 8) * 2;
    const uint32_t bLane = ((lane & 15) * B_STR + warp_n * 32 + (lane >> 4) * 8) * 2;

    float cacc[4][4][4];
    #pragma unroll
    for (int i = 0; i < 4; i++)
        #pragma unroll
        for (int j = 0; j < 4; j++)
            #pragma unroll
            for (int e = 0; e < 4; e++) cacc[i][j][e] = 0.f;

    #pragma unroll
    for (int s = 0; s < STAGES - 1; s++) {
        if (s < nc) prefetch(s, s);
        CP_COMMIT();
    }

    int stage = 0;
    for (int c = 0; c < nc; c++) {
        CP_WAIT1();
        __syncthreads();
        const uint32_t asB = dynB + stage * STAGE_BYTES;
        const uint32_t bsB = asB + AS_BYTES;
        #pragma unroll
        for (int kk = 0; kk < 4; kk++) {
            uint32_t af[4][4], bf[2][4];
            #pragma unroll
            for (int mf = 0; mf < 4; mf++)
                LDSM_X4(af[mf], asB + aLane + (mf * 16 * A_STR + kk * 16) * 2);
            #pragma unroll
            for (int nfp = 0; nfp < 2; nfp++)
                LDSM_X4T(bf[nfp], bsB + bLane + (kk * 16 * B_STR + nfp * 16) * 2);
            #pragma unroll
            for (int mf = 0; mf < 4; mf++)
                #pragma unroll
                for (int nfp = 0; nfp < 2; nfp++) {
                    MMA16816(cacc[mf][nfp * 2],     af[mf], bf[nfp][0], bf[nfp][1]);
                    MMA16816(cacc[mf][nfp * 2 + 1], af[mf], bf[nfp][2], bf[nfp][3]);
                }
        }
        int pc = c + STAGES - 1;
        int pstage = stage + STAGES - 1;
        if (pstage >= STAGES) pstage -= STAGES;
        if (pc < nc) prefetch(pc, pstage);
        CP_COMMIT();
        stage = (stage + 1 == STAGES) ? 0 : stage + 1;
    }

    {
        const int g = lane >> 2, t = lane & 3;
        #pragma unroll
        for (int mf = 0; mf < 4; mf++) {
            const int tr1 = warp_m * 64 + mf * 16 + g;
            const int tr2 = tr1 + 8;
            __half* o1 = sO[tr1];
            __half* o2 = sO[tr2];
            const float* ad1 = sAdd[tr1];
            const float* ad2 = sAdd[tr2];
            #pragma unroll
            for (int nf = 0; nf < 4; nf++) {
                const int col0 = nblk + warp_n * 32 + nf * 8 + t * 2;
                const float b0 = p.bias[col0], b1 = p.bias[col0 + 1];
                const float* cc = cacc[mf][nf];
                if (o1) {
                    float v0 = cc[0] + b0, v1 = cc[1] + b1;
                    if (MODE == M_LEAF && ad1) { v0 += ad1[col0]; v1 += ad1[col0 + 1]; }
                    if (DOTANH) { v0 = tanhf(v0); v1 = tanhf(v1); }
                    *reinterpret_cast<__half2*>(o1 + col0) = __floats2half2_rn(v0, v1);
                }
                if (o2) {
                    float v0 = cc[2] + b0, v1 = cc[3] + b1;
                    if (MODE == M_LEAF && ad2) { v0 += ad2[col0]; v1 += ad2[col0 + 1]; }
                    if (DOTANH) { v0 = tanhf(v0); v1 = tanhf(v1); }
                    *reinterpret_cast<__half2*>(o2 + col0) = __floats2half2_rn(v0, v1);
                }
            }
        }
    }
}

// ---------------- small-M fp16 GEMM: BK=64, 4 stages, single barrier/chunk ----------------
template<int MODE, bool DOTANH>
__global__ __launch_bounds__(256, 2) void hgemm_s(GP p) {
    __shared__ const __half* sAp[4][MT_S];
    __shared__ __half* sO[MT_S];
    extern __shared__ __align__(16) char dynraw[];

    const int tid = threadIdx.x;
    const int wid = tid >> 5;
    const int lane = tid & 31;
    const int rbase = blockIdx.y * MT_S;
    const int nblk = blockIdx.x * NTILE_S;

    if (tid < MT_S) {
        const __half *a0, *a1, *a2, *a3; const float* ad; __half* o;
        resolve_row<MODE>(p, rbase + tid, a0, a1, a2, a3, ad, o);
        sAp[0][tid] = a0; sAp[1][tid] = a1; sAp[2][tid] = a2; sAp[3][tid] = a3;
        sO[tid] = o;
    }
    __syncthreads();

    const int nc = p.Ktot / BK;
    int c0 = 0, ncc = nc;
    if (p.partial) {
        c0 = blockIdx.z * p.kcpz;
        ncc = nc - c0;
        if (ncc > p.kcpz) ncc = p.kcpz;
        if (ncc < 0) ncc = 0;
    }
    const uint32_t dynB = smem_u32(dynraw);

    auto prefetch = [&](int c, int stage) {
        const uint32_t asB = dynB + stage * STAGE_BYTES_S;
        const uint32_t bsB = asB + AS_BYTES_S;
        int phidx = 0;
        #pragma unroll
        for (int q = 1; q < 4; q++) if (q < p.nph && c >= p.ph_start[q]) phidx = q;
        const int kloc = (c - p.ph_start[phidx]) * BK;
        {
            int row = tid >> 3, seg = tid & 7;
            CP_ASYNC16(asB + (row * A_STR + seg * 8) * 2, sAp[phidx][row] + kloc + seg * 8);
        }
        const __half* wsrc = p.W + (size_t)(c * BK) * p.ldw + nblk;
        #pragma unroll
        for (int i = 0; i < 4; i++) {
            int lin = i * 256 + tid;
            int row = lin >> 4, seg = lin & 15;
            CP_ASYNC16(bsB + (row * BS_STR_S + seg * 8) * 2, wsrc + (size_t)row * p.ldw + seg * 8);
        }
    };

    const uint32_t aLane = ((lane & 15) * A_STR + (lane >> 4) * 8) * 2;
    const uint32_t bLane = ((lane & 15) * BS_STR_S + wid * 16 + (lane >> 4) * 8) * 2;

    float cacc[2][2][4];
    #pragma unroll
    for (int i = 0; i < 2; i++)
        #pragma unroll
        for (int j = 0; j < 2; j++)
            #pragma unroll
            for (int e = 0; e < 4; e++) cacc[i][j][e] = 0.f;

    #pragma unroll
    for (int s = 0; s < STAGES_S - 1; s++) {
        if (s < ncc) prefetch(c0 + s, s);
        CP_COMMIT();
    }

    for (int cc = 0; cc < ncc; cc++) {
        CP_WAIT2();
        __syncthreads();
        const int stage = cc & (STAGES_S - 1);
        const uint32_t asB = dynB + stage * STAGE_BYTES_S;
        const uint32_t bsB = asB + AS_BYTES_S;
        #pragma unroll
        for (int kk = 0; kk < 4; kk++) {
            uint32_t af[2][4], bf[4];
            #pragma unroll
            for (int mf = 0; mf < 2; mf++)
                LDSM_X4(af[mf], asB + aLane + (mf * 16 * A_STR + kk * 16) * 2);
            LDSM_X4T(bf, bsB + bLane + (kk * 16 * BS_STR_S) * 2);
            #pragma unroll
            for (int mf = 0; mf < 2; mf++) {
                MMA16816(cacc[mf][0], af[mf], bf[0], bf[1]);
                MMA16816(cacc[mf][1], af[mf], bf[2], bf[3]);
            }
        }
        int pcc = cc + STAGES_S - 1;
        if (pcc < ncc) prefetch(c0 + pcc, pcc & (STAGES_S - 1));
        CP_COMMIT();
    }

    {
        const int g = lane >> 2, t = lane & 3;
        if (p.partial) {
            float* base = p.partial + (size_t)blockIdx.z * p.M * p.Nout;
            #pragma unroll
            for (int mf = 0; mf < 2; mf++) {
                const int r1 = rbase + mf * 16 + g;
                const int r2 = r1 + 8;
                #pragma unroll
                for (int nf = 0; nf < 2; nf++) {
                    const int col0 = nblk + wid * 16 + nf * 8 + t * 2;
                    const float* cc = cacc[mf][nf];
                    if (r1 < p.M)
                        *reinterpret_cast<float2*>(base + (size_t)r1 * p.Nout + col0) =
                            make_float2(cc[0], cc[1]);
                    if (r2 < p.M)
                        *reinterpret_cast<float2*>(base + (size_t)r2 * p.Nout + col0) =
                            make_float2(cc[2], cc[3]);
                }
            }
        } else {
            #pragma unroll
            for (int mf = 0; mf < 2; mf++) {
                const int tr1 = mf * 16 + g;
                const int tr2 = tr1 + 8;
                __half* o1 = sO[tr1];
                __half* o2 = sO[tr2];
                #pragma unroll
                for (int nf = 0; nf < 2; nf++) {
                    const int col0 = nblk + wid * 16 + nf * 8 + t * 2;
                    const float b0 = p.bias[col0], b1 = p.bias[col0 + 1];
                    const float* cc = cacc[mf][nf];
                    if (o1) {
                        float v0 = cc[0] + b0, v1 = cc[1] + b1;
                        if (DOTANH) { v0 = tanhf(v0); v1 = tanhf(v1); }
                        *reinterpret_cast<__half2*>(o1 + col0) = __floats2half2_rn(v0, v1);
                    }
                    if (o2) {
                        float v0 = cc[2] + b0, v1 = cc[3] + b1;
                        if (DOTANH) { v0 = tanhf(v0); v1 = tanhf(v1); }
                        *reinterpret_cast<__half2*>(o2 + col0) = __floats2half2_rn(v0, v1);
                    }
                }
            }
        }
    }
}

// ---------------- split-K reduction ----------------
template<int MODE>
__global__ __launch_bounds__(256) void reduceK(GP p, int nz) {
    int idx = blockIdx.x * 256 + threadIdx.x;
    int halfN = p.Nout >> 1;
    int total = p.M * halfN;
    if (idx >= total) return;
    int row = idx / halfN;
    int col = (idx % halfN) * 2;
    const __half *a0, *a1, *a2, *a3; const float* ad; __half* o;
    resolve_row<MODE>(p, row, a0, a1, a2, a3, ad, o);
    if (!o) return;
    float v0 = p.bias[col], v1 = p.bias[col + 1];
    for (int z = 0; z < nz; z++) {
        const float* q = p.partial + ((size_t)z * p.M + row) * p.Nout + col;
        v0 += q[0]; v1 += q[1];
    }
    *reinterpret_cast<__half2*>(o + col) = __floats2half2_rn(tanhf(v0), tanhf(v1));
}

// ---------------- classifier ----------------
__global__ __launch_bounds__(256) void clf_kernel(const float* __restrict__ clfW,
                                                  const float* __restrict__ clfb,
                                                  float* __restrict__ out) {
    int row = blockIdx.x * 8 + (threadIdx.x >> 5);
    if (row >= BB * NSEQ) return;
    int lane = threadIdx.x & 31;
    const __half2* dn = reinterpret_cast<const __half2*>(g_down + (size_t)row * HH);
    const __half2* up = reinterpret_cast<const __half2*>(g_up   + (size_t)row * HH);
    float s0 = 0.f, s1 = 0.f, s2 = 0.f;
    for (int i = lane; i < 512; i += 32) {
        float2 d = __half22float2(dn[i]);
        float2 u = __half22float2(up[i]);
        int k = 2 * i;
        const float* w  = clfW + (size_t)k * 3;
        const float* w2 = clfW + (size_t)(k + HH) * 3;
        s0 += d.x * w[0] + d.y * w[3] + u.x * w2[0] + u.y * w2[3];
        s1 += d.x * w[1] + d.y * w[4] + u.x * w2[1] + u.y * w2[4];
        s2 += d.x * w[2] + d.y * w[5] + u.x * w2[2] + u.y * w2[5];
    }
    #pragma unroll
    for (int o = 16; o > 0; o >>= 1) {
        s0 += __shfl_xor_sync(0xFFFFFFFFu, s0, o);
        s1 += __shfl_xor_sync(0xFFFFFFFFu, s1, o);
        s2 += __shfl_xor_sync(0xFFFFFFFFu, s2, o);
    }
    if (lane == 0) {
        out[(size_t)row * 3 + 0] = tanhf(s0 + clfb[0]);
        out[(size_t)row * 3 + 1] = tanhf(s1 + clfb[1]);
        out[(size_t)row * 3 + 2] = tanhf(s2 + clfb[2]);
    }
}

// ---------------- host ----------------
extern "C" void kernel_launch(void* const* d_in, const int* in_sizes, int n_in,
                              void* d_out, int out_size) {
    (void)in_sizes; (void)n_in; (void)out_size;
    const int*   x     = (const int*)  d_in[0];
    const int*   cue   = (const int*)  d_in[2];
    const int*   pos   = (const int*)  d_in[4];
    const float* wemb  = (const float*)d_in[6];
    const float* syn   = (const float*)d_in[7];
    const float* leafW = (const float*)d_in[8];
    const float* leafb = (const float*)d_in[9];
    const float* compW = (const float*)d_in[10];
    const float* compb = (const float*)d_in[11];
    const float* grevW = (const float*)d_in[12];
    const float* grevb = (const float*)d_in[13];
    const float* decW  = (const float*)d_in[14];
    const float* decb  = (const float*)d_in[15];
    const float* clfW  = (const float*)d_in[16];
    const float* clfb  = (const float*)d_in[17];
    float* out = (float*)d_out;

    __half *wc, *wd, *wl, *wg;
    float* gp;
    cudaGetSymbolAddress((void**)&wc, g_wcomp);
    cudaGetSymbolAddress((void**)&wd, g_wdec);
    cudaGetSymbolAddress((void**)&wl, g_wleaf);
    cudaGetSymbolAddress((void**)&wg, g_wgrev);
    cudaGetSymbolAddress((void**)&gp, g_partial);

    cudaFuncSetAttribute(hgemm<M_LEAF, false>, cudaFuncAttributeMaxDynamicSharedMemorySize, DSMEM);
    cudaFuncSetAttribute(hgemm<M_UP,   true>,  cudaFuncAttributeMaxDynamicSharedMemorySize, DSMEM);
    cudaFuncSetAttribute(hgemm<M_DOWN, true>,  cudaFuncAttributeMaxDynamicSharedMemorySize, DSMEM);
    cudaFuncSetAttribute(hgemm_s<M_UP,   true>, cudaFuncAttributeMaxDynamicSharedMemorySize, DSMEM_S);
    cudaFuncSetAttribute(hgemm_s<M_GREV, true>, cudaFuncAttributeMaxDynamicSharedMemorySize, DSMEM_S);
    cudaFuncSetAttribute(hgemm_s<M_DOWN, true>, cudaFuncAttributeMaxDynamicSharedMemorySize, DSMEM_S);

    prep_all<<<1024, 256>>>(compW, decW, leafW, grevW, syn);
    build_leafA<<<(BB * LL + 7) / 8, 256>>>(x, pos, wemb, syn);

    GP base{};
    base.x = x; base.cue = cue; base.leafW = leafW;
    base.node_base = 0; base.node_cnt = 1;
    base.partial = nullptr; base.kcpz = 0;

    auto kslices_for = [](int ctas) -> int {
        if (ctas <= 32) return 8;
        if (ctas <= 64) return 4;
        return 1;
    };

    // leaf: K=1088 -> 17 chunks, 1 phase
    {
        GP q = base;
        q.W = wl; q.bias = leafb; q.ldw = 1024; q.Nout = 1024;
        q.M = BB * LL; q.Ktot = KP_LG; q.nph = 1;
        q.ph_start[0] = 0; q.ph_start[1] = 1 << 20; q.ph_start[2] = 1 << 20; q.ph_start[3] = 1 << 20;
        hgemm<M_LEAF, false><<<dim3(8, q.M / MT), 256, DSMEM>>>(q);
    }
    // up pass: syn = chunk 0, children = chunks 1..32
    for (int lvl = 8; lvl >= 0; lvl--) {
        int cnt = 1 << lvl;
        GP q = base;
        q.W = wc; q.bias = compb; q.ldw = 1024; q.Nout = 1024;
        q.M = BB * cnt; q.Ktot = KP_COMP; q.nph = 2;
        q.node_base = cnt - 1; q.node_cnt = cnt;
        q.ph_start[0] = 0; q.ph_start[1] = 1; q.ph_start[2] = 1 << 20; q.ph_start[3] = 1 << 20;
        if (q.M >= 4096) {
            hgemm<M_UP, true><<<dim3(8, q.M / MT), 256, DSMEM>>>(q);
        } else {
            int gx = 8, gy = q.M / MT_S;
            int ks = kslices_for(gx * gy);
            int nc = q.Ktot / BK;
            if (ks > 1) {
                q.partial = gp; q.kcpz = (nc + ks - 1) / ks;
                hgemm_s<M_UP, true><<<dim3(gx, gy, ks), 256, DSMEM_S>>>(q);
                int total = q.M * (q.Nout / 2);
                reduceK<M_UP><<<(total + 255) / 256, 256>>>(q, ks);
            } else {
                hgemm_s<M_UP, true><<<dim3(gx, gy), 256, DSMEM_S>>>(q);
            }
        }
    }
    // grev: up-root = chunks 0..15, syn = chunk 16
    {
        GP q = base;
        q.W = wg; q.bias = grevb; q.ldw = 1024; q.Nout = 1024;
        q.M = BB; q.Ktot = KP_LG; q.nph = 2;
        q.ph_start[0] = 0; q.ph_start[1] = 16; q.ph_start[2] = 1 << 20; q.ph_start[3] = 1 << 20;
        int ks = 8, nc = q.Ktot / BK;
        q.partial = gp; q.kcpz = (nc + ks - 1) / ks;
        hgemm_s<M_GREV, true><<<dim3(8, 1, ks), 256, DSMEM_S>>>(q);
        int total = q.M * (q.Nout / 2);
        reduceK<M_GREV><<<(total + 255) / 256, 256>>>(q, ks);
    }
    // down pass: syn_l=0, syn_r=1, down=2..17, up=18..33
    for (int lvl = 0; lvl < 9; lvl++) {
        int cnt = 1 << lvl;
        GP q = base;
        q.W = wd; q.bias = decb; q.ldw = 2048; q.Nout = 2048;
        q.M = BB * cnt; q.Ktot = KP_DEC; q.nph = 4;
        q.node_base = cnt - 1; q.node_cnt = cnt;
        q.cue = pos;
        q.ph_start[0] = 0; q.ph_start[1] = 1; q.ph_start[2] = 2; q.ph_start[3] = 18;
        if (q.M >= 4096) {
            hgemm<M_DOWN, true><<<dim3(16, q.M / MT), 256, DSMEM>>>(q);
        } else {
            int gx = 16, gy = q.M / MT_S;
            int ks = kslices_for(gx * gy);
            int nc = q.Ktot / BK;
            if (ks > 1) {
                q.partial = gp; q.kcpz = (nc + ks - 1) / ks;
                hgemm_s<M_DOWN, true><<<dim3(gx, gy, ks), 256, DSMEM_S>>>(q);
                int total = q.M * (q.Nout / 2);
                reduceK<M_DOWN><<<(total + 255) / 256, 256>>>(q, ks);
            } else {
                hgemm_s<M_DOWN, true><<<dim3(gx, gy), 256, DSMEM_S>>>(q);
            }
        }
    }
    clf_kernel<<<(BB * NSEQ + 7) / 8, 256>>>(clfW, clfb, out);
}